// round 3
// baseline (speedup 1.0000x reference)
#include <cuda_runtime.h>
#include <cuda_bf16.h>

// DenseRadiusGraph: B=16 graphs x N=2048 nodes, D=3, cutoff=10, K=32 nearest
// within cutoff. Output (float32 concat): row[M] | col[M] | w[M] | valid[M],
// M = B*N*K.
//
// Numerics: cutoff test + ordering must use the reference's GEMM-form distance
// sqrt(max(sq_i + sq_j - 2*dot, 0)) with plain (non-FMA) fp32 rounding and the
// same association; w uses the direct form sqrt((dx^2+dy^2)+dz^2), also
// non-FMA. A fast FMA-contracted d2 prescreen (margin +0.03) culls ~99.6% of
// candidates before the exact path.

#define BGR 16
#define NGR 2048
#define KNB 32
#define TPB 128

__global__ __launch_bounds__(TPB) void radius_graph_kernel(
    const float* __restrict__ pos,  // [B*N, 3]
    float* __restrict__ out,        // [4*M] floats
    int M)
{
    __shared__ float4 sh[NGR];  // {x, y, z, sq} per node of this graph

    const int b   = blockIdx.y;
    const int tid = threadIdx.x;

    // Load this graph's positions into shared, precompute sq = ((x*x+y*y)+z*z)
    // with the reference's rounding (no FMA).
    const float* gp = pos + (size_t)b * NGR * 3;
    for (int j = tid; j < NGR; j += TPB) {
        float x = gp[3 * j + 0];
        float y = gp[3 * j + 1];
        float z = gp[3 * j + 2];
        float sq = __fadd_rn(__fadd_rn(__fmul_rn(x, x), __fmul_rn(y, y)),
                             __fmul_rn(z, z));
        sh[j] = make_float4(x, y, z, sq);
    }
    __syncthreads();

    const int n = blockIdx.x * TPB + tid;  // local query index within graph
    const float4 q = sh[n];

    // Sorted candidate list (dist ascending, stable => lowest index first on ties)
    float dlist[KNB];
    int   ilist[KNB];
    int   cnt = 0;

    const float D2_SCREEN = 100.05f;  // exact boundary is ~100.0000191; FMA-vs-exact |delta| < 0.01

    #pragma unroll 8
    for (int j = 0; j < NGR; ++j) {
        float4 c = sh[j];
        // Fast screen: FMA contraction allowed here.
        float dot_f = q.x * c.x + q.y * c.y + q.z * c.z;
        float d2_f  = (q.w + c.w) - 2.0f * dot_f;
        if (d2_f <= D2_SCREEN && j != n) {
            // Exact reference-matching recompute (no FMA, fixed association).
            float m1 = __fmul_rn(q.x, c.x);
            float m2 = __fmul_rn(q.y, c.y);
            float m3 = __fmul_rn(q.z, c.z);
            float dote = __fadd_rn(__fadd_rn(m1, m2), m3);
            float t    = __fadd_rn(q.w, c.w);
            float d2   = __fsub_rn(t, __fmul_rn(2.0f, dote));
            float dist = __fsqrt_rn(fmaxf(d2, 0.0f));
            if (dist <= 10.0f) {
                if (cnt < KNB) {
                    int p = cnt;
                    while (p > 0 && dlist[p - 1] > dist) {  // stop at equal => stable
                        dlist[p] = dlist[p - 1];
                        ilist[p] = ilist[p - 1];
                        --p;
                    }
                    dlist[p] = dist;
                    ilist[p] = j;
                    ++cnt;
                } else if (dist < dlist[KNB - 1]) {  // strict <: equal keeps earlier index
                    int p = KNB - 1;
                    while (p > 0 && dlist[p - 1] > dist) {
                        dlist[p] = dlist[p - 1];
                        ilist[p] = ilist[p - 1];
                        --p;
                    }
                    dlist[p] = dist;
                    ilist[p] = j;
                }
            }
        }
    }

    // Emit outputs. Invalid slots -> zeros (reference zeroes row/col/w, valid=0).
    const int  g    = b * NGR + n;
    const long base = (long)g * KNB;
    float* rowp = out;
    float* colp = out + (long)M;
    float* wp   = out + 2L * (long)M;
    float* vp   = out + 3L * (long)M;

    #pragma unroll 1
    for (int k = 0; k < KNB; ++k) {
        float rv = 0.0f, cv = 0.0f, wv = 0.0f, vv = 0.0f;
        if (k < cnt) {
            int j = ilist[k];
            float4 c = sh[j];
            // w: direct-form distance, non-FMA, association ((dx^2+dy^2)+dz^2)
            float dx = __fsub_rn(q.x, c.x);
            float dy = __fsub_rn(q.y, c.y);
            float dz = __fsub_rn(q.z, c.z);
            float s  = __fadd_rn(__fadd_rn(__fmul_rn(dx, dx), __fmul_rn(dy, dy)),
                                 __fmul_rn(dz, dz));
            wv = __fsqrt_rn(s);
            rv = (float)g;
            cv = (float)(b * NGR + j);
            vv = 1.0f;
        }
        rowp[base + k] = rv;
        colp[base + k] = cv;
        wp[base + k]   = wv;
        vp[base + k]   = vv;
    }
}

extern "C" void kernel_launch(void* const* d_in, const int* in_sizes, int n_in,
                              void* d_out, int out_size) {
    const float* pos = (const float*)d_in[0];
    (void)in_sizes; (void)n_in;
    float* out = (float*)d_out;
    int M = out_size / 4;  // = B*N*K
    dim3 grid(NGR / TPB, BGR, 1);
    radius_graph_kernel<<<grid, TPB>>>(pos, out, M);
}

// round 4
// speedup vs baseline: 4.3579x; 4.3579x over previous
#include <cuda_runtime.h>
#include <cuda_bf16.h>

// DenseRadiusGraph: B=16 graphs x N=2048 nodes, D=3, cutoff=10, K=32 nearest
// within cutoff. Output (float32 concat): row[M] | col[M] | w[M] | valid[M].
//
// R4: one WARP per query node (was one thread). 64 chunks x 32 candidates,
// ballot screen, distributed warp top-K (lane l holds l-th smallest).
// Numerics identical to R3: screen uses FMA-contracted d2 with +0.05 margin;
// selection/ordering uses reference-rounded GEMM-form distance (no FMA,
// fixed association); w uses direct-form distance (no FMA).

#define BGR 16
#define NGR 2048
#define KNB 32
#define TPB 512           // 16 warps = 16 queries per block
#define QPB (TPB / 32)

__global__ __launch_bounds__(TPB) void radius_graph_warp_kernel(
    const float* __restrict__ pos,  // [B*N, 3]
    float* __restrict__ out,        // [4*M] floats
    int M)
{
    __shared__ float4 sh[NGR];  // {x, y, z, sq} per node of this graph

    const int b    = blockIdx.y;
    const int tid  = threadIdx.x;
    const int warp = tid >> 5;
    const int lane = tid & 31;
    const unsigned FULL = 0xffffffffu;

    // Cooperative load of this graph's positions; sq with reference rounding.
    const float* gp = pos + (size_t)b * NGR * 3;
    for (int j = tid; j < NGR; j += TPB) {
        float x = gp[3 * j + 0];
        float y = gp[3 * j + 1];
        float z = gp[3 * j + 2];
        float sq = __fadd_rn(__fadd_rn(__fmul_rn(x, x), __fmul_rn(y, y)),
                             __fmul_rn(z, z));
        sh[j] = make_float4(x, y, z, sq);
    }
    __syncthreads();

    const int n = blockIdx.x * QPB + warp;   // local query index in graph
    const float4 q = sh[n];                  // broadcast read

    // Distributed sorted neighbor list: lane l holds l-th smallest (dist, idx).
    const float INF = __int_as_float(0x7f800000);
    float kd = INF;
    int   ki = 0;

    const float D2_SCREEN = 100.05f;

    #pragma unroll 4
    for (int chunk = 0; chunk < NGR / 32; ++chunk) {
        const int j = chunk * 32 + lane;
        float4 c = sh[j];
        // Fast screen (FMA contraction fine here).
        float dot_f = q.x * c.x + q.y * c.y + q.z * c.z;
        float d2_f  = (q.w + c.w) - 2.0f * dot_f;
        unsigned mask = __ballot_sync(FULL, d2_f <= D2_SCREEN);
        if (mask) {
            // Exact reference-matching recompute for every lane in the chunk.
            float m1 = __fmul_rn(q.x, c.x);
            float m2 = __fmul_rn(q.y, c.y);
            float m3 = __fmul_rn(q.z, c.z);
            float dote = __fadd_rn(__fadd_rn(m1, m2), m3);
            float t    = __fadd_rn(q.w, c.w);
            float d2   = __fsub_rn(t, __fmul_rn(2.0f, dote));
            float de   = __fsqrt_rn(fmaxf(d2, 0.0f));
            unsigned emask = __ballot_sync(FULL, (de <= 10.0f) && (j != n));
            // Insert each hit (ascending j => stable lowest-index-first ties).
            while (emask) {
                int src = __ffs(emask) - 1;
                emask &= emask - 1;
                float d  = __shfl_sync(FULL, de, src);
                int   jj = chunk * 32 + src;
                // Position: existing entries with kd <= d stay before (stable).
                int p = __popc(__ballot_sync(FULL, kd <= d));
                float sd = __shfl_up_sync(FULL, kd, 1);
                int   si = __shfl_up_sync(FULL, ki, 1);
                if (p < 32) {
                    if (lane == p)      { kd = d;  ki = jj; }
                    else if (lane > p)  { kd = sd; ki = si; }
                }
            }
        }
    }

    // Emit: lane l writes slot l. Invalid -> zeros, valid flag 0.
    const int  g    = b * NGR + n;
    const long base = (long)g * KNB;
    float* rowp = out;
    float* colp = out + (long)M;
    float* wp   = out + 2L * (long)M;
    float* vp   = out + 3L * (long)M;

    float rv = 0.0f, cv = 0.0f, wv = 0.0f, vv = 0.0f;
    if (kd < INF) {
        float4 c = sh[ki];
        // w: direct-form distance, non-FMA, association ((dx^2+dy^2)+dz^2).
        float dx = __fsub_rn(q.x, c.x);
        float dy = __fsub_rn(q.y, c.y);
        float dz = __fsub_rn(q.z, c.z);
        float s  = __fadd_rn(__fadd_rn(__fmul_rn(dx, dx), __fmul_rn(dy, dy)),
                             __fmul_rn(dz, dz));
        wv = __fsqrt_rn(s);
        rv = (float)g;
        cv = (float)(b * NGR + ki);
        vv = 1.0f;
    }
    rowp[base + lane] = rv;
    colp[base + lane] = cv;
    wp[base + lane]   = wv;
    vp[base + lane]   = vv;
}

extern "C" void kernel_launch(void* const* d_in, const int* in_sizes, int n_in,
                              void* d_out, int out_size) {
    const float* pos = (const float*)d_in[0];
    (void)in_sizes; (void)n_in;
    float* out = (float*)d_out;
    int M = out_size / 4;  // = B*N*K
    dim3 grid(NGR / QPB, BGR, 1);
    radius_graph_warp_kernel<<<grid, TPB>>>(pos, out, M);
}

// round 5
// speedup vs baseline: 8.6806x; 1.9919x over previous
#include <cuda_runtime.h>
#include <cuda_bf16.h>

// DenseRadiusGraph R5: cell-list accelerated K=32-nearest-within-cutoff.
// B=16 graphs x N=2048 nodes, box 100, cutoff 10. Cells of side 20 (5^3 per
// graph, ~16.4 nodes each); a query only scans the <=27 (typically 8) cells
// overlapping its +-10 ball => ~131 candidates instead of 2048.
//
// Numerics: selection/ordering uses the reference's GEMM-form distance with
// plain fp32 rounding (no FMA, fixed association); sqrt gated by d2<=100.001.
// Ties broken lexicographically by (dist, index) == top_k's lowest-index-first,
// making the result independent of the nondeterministic atomic scatter order.

#define BGR   16
#define NGR   2048
#define KNB   32
#define NCD   5
#define NCELL 125          // 5^3
#define TPB   256
#define QPB   (TPB / 32)   // queries (warps) per block

// Scratch (device globals: no allocation allowed).
__device__ float4 g_sorted[BGR * NGR];          // cell-sorted {x,y,z,sq}
__device__ int    g_sidx[BGR * NGR];            // original local index
__device__ int    g_cellstart[BGR * NCELL + 1]; // absolute start offsets (+sentinel)
__device__ int    g_count[BGR * NCELL];
__device__ int    g_cursor[BGR * NCELL];

__device__ __forceinline__ int cell_clamp(float v) {
    int c = __float2int_rd(v * 0.05f);   // /20
    return min(NCD - 1, max(0, c));
}

// ---- build kernels -------------------------------------------------------

__global__ void k_zero() {
    int i = blockIdx.x * blockDim.x + threadIdx.x;
    if (i < BGR * NCELL) g_count[i] = 0;
}

__global__ void k_histo(const float* __restrict__ pos) {
    int i = blockIdx.x * blockDim.x + threadIdx.x;
    if (i >= BGR * NGR) return;
    int b = i >> 11;  // /NGR
    float x = pos[3 * i + 0], y = pos[3 * i + 1], z = pos[3 * i + 2];
    int cid = (cell_clamp(z) * NCD + cell_clamp(y)) * NCD + cell_clamp(x);
    atomicAdd(&g_count[b * NCELL + cid], 1);
}

__global__ void k_scan() {  // single block, TPB threads
    __shared__ int sc[BGR * NCELL];
    for (int i = threadIdx.x; i < BGR * NCELL; i += blockDim.x)
        sc[i] = g_count[i];
    __syncthreads();
    int t = threadIdx.x;
    if (t < BGR) {
        int off = t * NGR;
        for (int c = 0; c < NCELL; ++c) {
            g_cellstart[t * NCELL + c] = off;
            g_cursor[t * NCELL + c]    = off;
            off += sc[t * NCELL + c];
        }
    }
    if (t == 0) g_cellstart[BGR * NCELL] = BGR * NGR;
}

__global__ void k_scatter(const float* __restrict__ pos) {
    int i = blockIdx.x * blockDim.x + threadIdx.x;
    if (i >= BGR * NGR) return;
    int b = i >> 11;
    float x = pos[3 * i + 0], y = pos[3 * i + 1], z = pos[3 * i + 2];
    float sq = __fadd_rn(__fadd_rn(__fmul_rn(x, x), __fmul_rn(y, y)),
                         __fmul_rn(z, z));
    int cid  = (cell_clamp(z) * NCD + cell_clamp(y)) * NCD + cell_clamp(x);
    int slot = atomicAdd(&g_cursor[b * NCELL + cid], 1);
    g_sorted[slot] = make_float4(x, y, z, sq);
    g_sidx[slot]   = i - (b << 11);  // local index within graph
}

// ---- main search kernel --------------------------------------------------

__global__ __launch_bounds__(TPB) void k_search(
    const float* __restrict__ pos, float* __restrict__ out, int M)
{
    const int b    = blockIdx.y;
    const int warp = threadIdx.x >> 5;
    const int lane = threadIdx.x & 31;
    const unsigned FULL = 0xffffffffu;

    const int n = blockIdx.x * QPB + warp;        // local query index
    const float* gp = pos + (size_t)b * NGR * 3;
    float qx = gp[3 * n + 0], qy = gp[3 * n + 1], qz = gp[3 * n + 2];
    float qw = __fadd_rn(__fadd_rn(__fmul_rn(qx, qx), __fmul_rn(qy, qy)),
                         __fmul_rn(qz, qz));

    // Cell ranges covering the +-10 ball (+margin for GEMM-form d2 error).
    const int x0 = cell_clamp(qx - 10.01f), x1 = cell_clamp(qx + 10.01f);
    const int y0 = cell_clamp(qy - 10.01f), y1 = cell_clamp(qy + 10.01f);
    const int z0 = cell_clamp(qz - 10.01f), z1 = cell_clamp(qz + 10.01f);

    const float INF = __int_as_float(0x7f800000);
    float kd = INF;   // lane l holds l-th smallest (dist, idx)
    int   ki = -1;

    for (int cz = z0; cz <= z1; ++cz) {
        for (int cy = y0; cy <= y1; ++cy) {
            int rowbase = b * NCELL + (cz * NCD + cy) * NCD;
            int s = g_cellstart[rowbase + x0];
            int e = g_cellstart[rowbase + x1 + 1];  // contiguous x-run
            for (int t0 = s; t0 < e; t0 += 32) {
                int  t   = t0 + lane;
                bool act = t < e;
                float4 c = act ? g_sorted[t] : make_float4(0.f, 0.f, 0.f, 1e30f);
                // Reference-rounded GEMM-form d2 (no FMA, fixed association).
                float m1 = __fmul_rn(qx, c.x);
                float m2 = __fmul_rn(qy, c.y);
                float m3 = __fmul_rn(qz, c.z);
                float dote = __fadd_rn(__fadd_rn(m1, m2), m3);
                float tt   = __fadd_rn(qw, c.w);
                float d2   = __fsub_rn(tt, __fmul_rn(2.0f, dote));
                float de = INF;
                int   jl = n;  // self => excluded
                if (act && d2 <= 100.001f) {
                    de = __fsqrt_rn(fmaxf(d2, 0.0f));
                    jl = g_sidx[t];
                }
                unsigned emask = __ballot_sync(FULL, (de <= 10.0f) && (jl != n));
                while (emask) {
                    int src = __ffs(emask) - 1;
                    emask &= emask - 1;
                    float d  = __shfl_sync(FULL, de, src);
                    int   jj = __shfl_sync(FULL, jl, src);
                    // entries strictly before (d,jj) lexicographically stay put
                    int p = __popc(__ballot_sync(FULL,
                                (kd < d) || (kd == d && ki < jj)));
                    float sd = __shfl_up_sync(FULL, kd, 1);
                    int   si = __shfl_up_sync(FULL, ki, 1);
                    if (p < 32) {
                        if (lane == p)     { kd = d;  ki = jj; }
                        else if (lane > p) { kd = sd; ki = si; }
                    }
                }
            }
        }
    }

    // Emit: lane l writes slot l of this query's K row. Invalid -> zeros.
    const int  g    = b * NGR + n;
    const long base = (long)g * KNB;
    float* rowp = out;
    float* colp = out + (long)M;
    float* wp   = out + 2L * (long)M;
    float* vp   = out + 3L * (long)M;

    float rv = 0.0f, cv = 0.0f, wv = 0.0f, vv = 0.0f;
    if (kd < INF) {
        float cxp = gp[3 * ki + 0], cyp = gp[3 * ki + 1], czp = gp[3 * ki + 2];
        // w: direct-form distance, non-FMA, association ((dx^2+dy^2)+dz^2).
        float dx = __fsub_rn(qx, cxp);
        float dy = __fsub_rn(qy, cyp);
        float dz = __fsub_rn(qz, czp);
        float ss = __fadd_rn(__fadd_rn(__fmul_rn(dx, dx), __fmul_rn(dy, dy)),
                             __fmul_rn(dz, dz));
        wv = __fsqrt_rn(ss);
        rv = (float)g;
        cv = (float)(b * NGR + ki);
        vv = 1.0f;
    }
    rowp[base + lane] = rv;
    colp[base + lane] = cv;
    wp[base + lane]   = wv;
    vp[base + lane]   = vv;
}

// ---- launch --------------------------------------------------------------

extern "C" void kernel_launch(void* const* d_in, const int* in_sizes, int n_in,
                              void* d_out, int out_size) {
    const float* pos = (const float*)d_in[0];
    (void)in_sizes; (void)n_in;
    float* out = (float*)d_out;
    int M = out_size / 4;

    int nodes = BGR * NGR;
    k_zero<<<(BGR * NCELL + 255) / 256, 256>>>();
    k_histo<<<(nodes + 255) / 256, 256>>>(pos);
    k_scan<<<1, TPB>>>();
    k_scatter<<<(nodes + 255) / 256, 256>>>(pos);
    dim3 grid(NGR / QPB, BGR, 1);
    k_search<<<grid, TPB>>>(pos, out, M);
}

// round 7
// speedup vs baseline: 11.2594x; 1.2971x over previous
#include <cuda_runtime.h>
#include <cuda_bf16.h>

// DenseRadiusGraph R6: fused one-kernel cell-list build + anisotropic cells.
// B=16 graphs x N=2048 nodes, box 100, cutoff 10, K=32.
// Cells: x side 10 (10 cells), y/z side 20 (5 cells) => 250 cells/graph,
// ~8.2 nodes/cell. Query scans ~4 (cy,cz) rows; each row's x-run is one
// contiguous ~23-node range => ~1 warp chunk per row.
//
// Numerics (unchanged from R5): selection/ordering uses the reference's
// GEMM-form distance with plain fp32 rounding (no FMA, fixed association);
// ties broken lexicographically by (dist, index) == top_k lowest-index-first,
// independent of nondeterministic scatter order. w = direct-form, non-FMA.

#define BGR   16
#define NGR   2048
#define KNB   32
#define NCX   10
#define NCYZ  5
#define NCELL (NCX * NCYZ * NCYZ)   // 250
#define TPB   256
#define QPB   (TPB / 32)
#define BT    256                    // build threads per block
#define NPT   (NGR / BT)             // 8 nodes per build thread

// Scratch (device globals: no allocation allowed).
__device__ float4 g_sorted[BGR * NGR];          // cell-sorted {x,y,z,sq}
__device__ int    g_sidx[BGR * NGR];            // original local index
__device__ int    g_cellstart[BGR * NCELL + 1]; // absolute offsets (+sentinel)

__device__ __forceinline__ int clamp_x(float v) {
    int c = __float2int_rd(v * 0.1f);            // /10
    return min(NCX - 1, max(0, c));
}
__device__ __forceinline__ int clamp_yz(float v) {
    int c = __float2int_rd(v * 0.05f);           // /20
    return min(NCYZ - 1, max(0, c));
}

// ---- fused build: one CTA per graph -------------------------------------

__global__ __launch_bounds__(BT) void k_build(const float* __restrict__ pos) {
    __shared__ int s_cnt[NCELL];
    __shared__ int s_scan[BT];      // >= NCELL
    __shared__ int s_cur[NCELL];

    const int b = blockIdx.x;
    const int t = threadIdx.x;
    const float* gp = pos + (size_t)b * NGR * 3;

    for (int i = t; i < NCELL; i += BT) s_cnt[i] = 0;
    __syncthreads();

    // Phase 1: load nodes, compute cell ids, histogram.
    float px[NPT], py[NPT], pz[NPT];
    int   cid[NPT];
    #pragma unroll
    for (int k = 0; k < NPT; ++k) {
        int n = t + k * BT;
        px[k] = gp[3 * n + 0];
        py[k] = gp[3 * n + 1];
        pz[k] = gp[3 * n + 2];
        cid[k] = (clamp_yz(pz[k]) * NCYZ + clamp_yz(py[k])) * NCX + clamp_x(px[k]);
        atomicAdd(&s_cnt[cid[k]], 1);
    }
    __syncthreads();

    // Phase 2: exclusive scan of 250 counters (Hillis-Steele over 256 lanes).
    int v = (t < NCELL) ? s_cnt[t] : 0;
    s_scan[t] = v;
    __syncthreads();
    #pragma unroll
    for (int d = 1; d < BT; d <<= 1) {
        int u = (t >= d) ? s_scan[t - d] : 0;
        __syncthreads();
        s_scan[t] += u;
        __syncthreads();
    }
    if (t < NCELL) {
        int excl = s_scan[t] - v;
        s_cur[t] = excl;
        g_cellstart[b * NCELL + t] = b * NGR + excl;
    }
    if (b == BGR - 1 && t == 0) g_cellstart[BGR * NCELL] = BGR * NGR;
    __syncthreads();

    // Phase 3: scatter via shared atomic cursors.
    const int base = b * NGR;
    #pragma unroll
    for (int k = 0; k < NPT; ++k) {
        int slot = base + atomicAdd(&s_cur[cid[k]], 1);
        float sq = __fadd_rn(__fadd_rn(__fmul_rn(px[k], px[k]),
                                       __fmul_rn(py[k], py[k])),
                             __fmul_rn(pz[k], pz[k]));
        g_sorted[slot] = make_float4(px[k], py[k], pz[k], sq);
        g_sidx[slot]   = t + k * BT;
    }
}

// ---- search: one warp per query -----------------------------------------

__global__ __launch_bounds__(TPB) void k_search(
    const float* __restrict__ pos, float* __restrict__ out, int M)
{
    const int b    = blockIdx.y;
    const int warp = threadIdx.x >> 5;
    const int lane = threadIdx.x & 31;
    const unsigned FULL = 0xffffffffu;

    const int n = blockIdx.x * QPB + warp;
    const float* gp = pos + (size_t)b * NGR * 3;
    float qx = gp[3 * n + 0], qy = gp[3 * n + 1], qz = gp[3 * n + 2];
    float qw = __fadd_rn(__fadd_rn(__fmul_rn(qx, qx), __fmul_rn(qy, qy)),
                         __fmul_rn(qz, qz));

    const int x0 = clamp_x(qx - 10.01f),  x1 = clamp_x(qx + 10.01f);
    const int y0 = clamp_yz(qy - 10.01f), y1 = clamp_yz(qy + 10.01f);
    const int z0 = clamp_yz(qz - 10.01f), z1 = clamp_yz(qz + 10.01f);

    const float INF = __int_as_float(0x7f800000);
    float kd = INF;   // lane l holds l-th smallest (dist, idx)
    int   ki = -1;

    for (int cz = z0; cz <= z1; ++cz) {
        for (int cy = y0; cy <= y1; ++cy) {
            int rowbase = b * NCELL + (cz * NCYZ + cy) * NCX;
            int s = g_cellstart[rowbase + x0];
            int e = g_cellstart[rowbase + x1 + 1];  // contiguous x-run
            for (int t0 = s; t0 < e; t0 += 32) {
                int  t   = t0 + lane;
                bool act = t < e;
                float4 c = act ? g_sorted[t] : make_float4(0.f, 0.f, 0.f, 1e30f);
                // Reference-rounded GEMM-form d2 (no FMA, fixed association).
                float m1 = __fmul_rn(qx, c.x);
                float m2 = __fmul_rn(qy, c.y);
                float m3 = __fmul_rn(qz, c.z);
                float dote = __fadd_rn(__fadd_rn(m1, m2), m3);
                float tt   = __fadd_rn(qw, c.w);
                float d2   = __fsub_rn(tt, __fmul_rn(2.0f, dote));
                float de = INF;
                int   jl = n;  // self => excluded
                if (act && d2 <= 100.001f) {
                    de = __fsqrt_rn(fmaxf(d2, 0.0f));
                    jl = g_sidx[t];
                }
                unsigned emask = __ballot_sync(FULL, (de <= 10.0f) && (jl != n));
                while (emask) {
                    int src = __ffs(emask) - 1;
                    emask &= emask - 1;
                    float d  = __shfl_sync(FULL, de, src);
                    int   jj = __shfl_sync(FULL, jl, src);
                    int p = __popc(__ballot_sync(FULL,
                                (kd < d) || (kd == d && ki < jj)));
                    float sd = __shfl_up_sync(FULL, kd, 1);
                    int   si = __shfl_up_sync(FULL, ki, 1);
                    if (p < 32) {
                        if (lane == p)     { kd = d;  ki = jj; }
                        else if (lane > p) { kd = sd; ki = si; }
                    }
                }
            }
        }
    }

    // Emit: lane l writes slot l. Invalid -> zeros.
    const int  g    = b * NGR + n;
    const long base = (long)g * KNB;
    float* rowp = out;
    float* colp = out + (long)M;
    float* wp   = out + 2L * (long)M;
    float* vp   = out + 3L * (long)M;

    float rv = 0.0f, cv = 0.0f, wv = 0.0f, vv = 0.0f;
    if (kd < INF) {
        float cxp = gp[3 * ki + 0], cyp = gp[3 * ki + 1], czp = gp[3 * ki + 2];
        float dx = __fsub_rn(qx, cxp);
        float dy = __fsub_rn(qy, cyp);
        float dz = __fsub_rn(qz, czp);
        float ss = __fadd_rn(__fadd_rn(__fmul_rn(dx, dx), __fmul_rn(dy, dy)),
                             __fmul_rn(dz, dz));
        wv = __fsqrt_rn(ss);
        rv = (float)g;
        cv = (float)(b * NGR + ki);
        vv = 1.0f;
    }
    rowp[base + lane] = rv;
    colp[base + lane] = cv;
    wp[base + lane]   = wv;
    vp[base + lane]   = vv;
}

// ---- launch --------------------------------------------------------------

extern "C" void kernel_launch(void* const* d_in, const int* in_sizes, int n_in,
                              void* d_out, int out_size) {
    const float* pos = (const float*)d_in[0];
    (void)in_sizes; (void)n_in;
    float* out = (float*)d_out;
    int M = out_size / 4;

    k_build<<<BGR, BT>>>(pos);
    dim3 grid(NGR / QPB, BGR, 1);
    k_search<<<grid, TPB>>>(pos, out, M);
}